// round 13
// baseline (speedup 1.0000x reference)
#include <cuda_runtime.h>
#include <math.h>
#include <stdint.h>

// Problem constants
#define Bb 16
#define Ss 512
#define Hh 768
#define Tt 2
#define Nn 32
#define Ll 64
#define Ee 8
#define Dd 128
#define Aa 128

#define INV_SQRT_D 0.08838834764831845f
#define NQKV 1024   // fused q|k|v output width: 128+128+768

// sdpa_msgs dynamic smem: tile + qk + p + red + qbs
#define SDPA_SMEM_FLOATS (Ll * Hh + Ee * Hh + Ee * Ll + 256 + 8)
#define SDPA_SMEM_BYTES  (SDPA_SMEM_FLOATS * 4)

// ---------------- scratch (device globals; no allocation) ----------------
__device__ __align__(16) float g_x[Bb * Ss * Hh];            // updated sequence
__device__ __align__(16) float g_efea[Bb * Tt * Ee * Hh];    // gathered entity spans
__device__ __align__(16) float g_q[Bb * Tt * Ee * Dd];       // entity q proj
__device__ __align__(16) float g_qk[Bb * Tt * Ee * Hh];      // q @ Wk^T (folded k-proj)
__device__ __align__(16) float g_qb[Bb * Tt * Ee];           // q . bk
__device__ __align__(16) float g_msgs[Bb * Tt * Nn * Ee * Hh];
__device__ __align__(16) float g_spool[Bb * Tt * Nn];
__device__ __align__(16) float g_fbias[Bb * Tt];
__device__ __align__(16) float g_score[Bb * Tt * Nn];
__device__ __align__(16) float g_u1[Hh];
__device__ __align__(16) float g_u2[Hh];
__device__ float g_cb;
__device__ __align__(16) float g_Wqkv[Hh * NQKV];   // [768,1024] = Wq|Wk|Wv
__device__ __align__(16) float g_bqkv[NQKV];
__device__ __align__(16) float g_qkv[Bb * Ss * NQKV]; // q2|k2|v2 fused
__device__ __align__(16) float g_P[Bb * Ss * Ss];

// ---------------- tf32 helpers ----------------
__device__ __forceinline__ uint32_t f2tf(float x) {
    uint32_t r;
    asm("cvt.rna.tf32.f32 %0, %1;" : "=r"(r) : "f"(x));
    return r;
}
__device__ __forceinline__ void mma8(float* c, const uint32_t* a, const uint32_t* b) {
    asm volatile(
        "mma.sync.aligned.m16n8k8.row.col.f32.tf32.tf32.f32 "
        "{%0,%1,%2,%3},{%4,%5,%6,%7},{%8,%9},{%0,%1,%2,%3};"
        : "+f"(c[0]), "+f"(c[1]), "+f"(c[2]), "+f"(c[3])
        : "r"(a[0]), "r"(a[1]), "r"(a[2]), "r"(a[3]), "r"(b[0]), "r"(b[1]));
}

// ---------------- tf32 tensor-core GEMM ----------------
// C[M,N] = alpha * A[M,K] @ B (+ bias[N]); TB=true: B is [N,K] (C = A @ B^T).
// CTA tile 128x128, warp tile 64x32 (2x4 warps), K-stage 16, double buffered.
template <bool TB>
__global__ void __launch_bounds__(256, 2) tgemm(
    const float* __restrict__ A, const float* __restrict__ Bm,
    const float* __restrict__ bias, float* __restrict__ C,
    int M, int N, int K, int lda, int ldb, int ldc,
    long sA, long sB, long sC, float alpha) {
    __shared__ uint32_t As[2][16][132];
    __shared__ uint32_t Bs[2][16][132];
    int tid = threadIdx.x;
    long bz = blockIdx.z;
    A += bz * sA;
    Bm += bz * sB;
    C += bz * sC;
    int row0 = blockIdx.y * 128, col0 = blockIdx.x * 128;
    int wid = tid >> 5, lane = tid & 31;
    int wm = wid >> 2, wn = wid & 3;      // 2 x 4 warp grid
    int gid = lane >> 2, t4 = lane & 3;

    int ar = tid >> 1, ac = (tid & 1) * 8;         // A: 128 rows x 16 k
    const float* Ap = A + (long)(row0 + ar) * lda + ac;
    const float* Bp;
    int br, bc;
    if (TB) {
        br = tid >> 1; bc = (tid & 1) * 8;         // B^T: 128 n-rows x 16 k
        Bp = Bm + (long)(col0 + br) * ldb + bc;
    } else {
        br = tid >> 4; bc = (tid & 15) * 8;        // B: 16 k-rows x 128 n
        Bp = Bm + (long)br * ldb + col0 + bc;
    }

    float4 av0 = *(const float4*)Ap;
    float4 av1 = *(const float4*)(Ap + 4);
    float4 bv0 = *(const float4*)Bp;
    float4 bv1 = *(const float4*)(Bp + 4);

    float acc[4][4][4];
#pragma unroll
    for (int mi = 0; mi < 4; mi++)
#pragma unroll
        for (int ni = 0; ni < 4; ni++)
#pragma unroll
            for (int j = 0; j < 4; j++) acc[mi][ni][j] = 0.f;

    int nst = K / 16;

    {
        As[0][ac + 0][ar] = f2tf(av0.x); As[0][ac + 1][ar] = f2tf(av0.y);
        As[0][ac + 2][ar] = f2tf(av0.z); As[0][ac + 3][ar] = f2tf(av0.w);
        As[0][ac + 4][ar] = f2tf(av1.x); As[0][ac + 5][ar] = f2tf(av1.y);
        As[0][ac + 6][ar] = f2tf(av1.z); As[0][ac + 7][ar] = f2tf(av1.w);
        if (TB) {
            Bs[0][bc + 0][br] = f2tf(bv0.x); Bs[0][bc + 1][br] = f2tf(bv0.y);
            Bs[0][bc + 2][br] = f2tf(bv0.z); Bs[0][bc + 3][br] = f2tf(bv0.w);
            Bs[0][bc + 4][br] = f2tf(bv1.x); Bs[0][bc + 5][br] = f2tf(bv1.y);
            Bs[0][bc + 6][br] = f2tf(bv1.z); Bs[0][bc + 7][br] = f2tf(bv1.w);
        } else {
            uint4 u0 = {f2tf(bv0.x), f2tf(bv0.y), f2tf(bv0.z), f2tf(bv0.w)};
            uint4 u1 = {f2tf(bv1.x), f2tf(bv1.y), f2tf(bv1.z), f2tf(bv1.w)};
            *(uint4*)&Bs[0][br][bc] = u0;
            *(uint4*)&Bs[0][br][bc + 4] = u1;
        }
    }
    __syncthreads();

    for (int t = 0; t < nst; t++) {
        int cur = t & 1;
        if (t + 1 < nst) {
            Ap += 16;
            av0 = *(const float4*)Ap;
            av1 = *(const float4*)(Ap + 4);
            if (TB) Bp += 16; else Bp += (long)16 * ldb;
            bv0 = *(const float4*)Bp;
            bv1 = *(const float4*)(Bp + 4);
        }
#pragma unroll
        for (int kk = 0; kk < 2; kk++) {
            int kb = kk * 8;
            uint32_t af[4][4], bf[4][2];
#pragma unroll
            for (int mi = 0; mi < 4; mi++) {
                int r = wm * 64 + mi * 16 + gid;
                af[mi][0] = As[cur][kb + t4][r];
                af[mi][1] = As[cur][kb + t4][r + 8];
                af[mi][2] = As[cur][kb + t4 + 4][r];
                af[mi][3] = As[cur][kb + t4 + 4][r + 8];
            }
#pragma unroll
            for (int ni = 0; ni < 4; ni++) {
                int c = wn * 32 + ni * 8 + gid;
                bf[ni][0] = Bs[cur][kb + t4][c];
                bf[ni][1] = Bs[cur][kb + t4 + 4][c];
            }
#pragma unroll
            for (int mi = 0; mi < 4; mi++)
#pragma unroll
                for (int ni = 0; ni < 4; ni++) mma8(acc[mi][ni], af[mi], bf[ni]);
        }
        if (t + 1 < nst) {
            int nb = cur ^ 1;
            As[nb][ac + 0][ar] = f2tf(av0.x); As[nb][ac + 1][ar] = f2tf(av0.y);
            As[nb][ac + 2][ar] = f2tf(av0.z); As[nb][ac + 3][ar] = f2tf(av0.w);
            As[nb][ac + 4][ar] = f2tf(av1.x); As[nb][ac + 5][ar] = f2tf(av1.y);
            As[nb][ac + 6][ar] = f2tf(av1.z); As[nb][ac + 7][ar] = f2tf(av1.w);
            if (TB) {
                Bs[nb][bc + 0][br] = f2tf(bv0.x); Bs[nb][bc + 1][br] = f2tf(bv0.y);
                Bs[nb][bc + 2][br] = f2tf(bv0.z); Bs[nb][bc + 3][br] = f2tf(bv0.w);
                Bs[nb][bc + 4][br] = f2tf(bv1.x); Bs[nb][bc + 5][br] = f2tf(bv1.y);
                Bs[nb][bc + 6][br] = f2tf(bv1.z); Bs[nb][bc + 7][br] = f2tf(bv1.w);
            } else {
                uint4 u0 = {f2tf(bv0.x), f2tf(bv0.y), f2tf(bv0.z), f2tf(bv0.w)};
                uint4 u1 = {f2tf(bv1.x), f2tf(bv1.y), f2tf(bv1.z), f2tf(bv1.w)};
                *(uint4*)&Bs[nb][br][bc] = u0;
                *(uint4*)&Bs[nb][br][bc + 4] = u1;
            }
            __syncthreads();
        }
    }

#pragma unroll
    for (int mi = 0; mi < 4; mi++) {
        int row = row0 + wm * 64 + mi * 16 + gid;
#pragma unroll
        for (int ni = 0; ni < 4; ni++) {
            int col = col0 + wn * 32 + ni * 8 + t4 * 2;
            float b0 = bias ? bias[col] : 0.f;
            float b1 = bias ? bias[col + 1] : 0.f;
            float2 o0 = {acc[mi][ni][0] * alpha + b0, acc[mi][ni][1] * alpha + b1};
            float2 o1 = {acc[mi][ni][2] * alpha + b0, acc[mi][ni][3] * alpha + b1};
            *(float2*)&C[(long)row * ldc + col] = o0;
            *(float2*)&C[(long)(row + 8) * ldc + col] = o1;
        }
    }
}

// ---------------- u1/u2/cb precompute ----------------
__global__ void prep_u(const float* __restrict__ Ww, const float* __restrict__ Wa,
                       const float* __restrict__ bw, const float* __restrict__ ba) {
    int h = blockIdx.x * 256 + threadIdx.x;
    if (h < Hh) {
        float u1 = 0.f, u2 = 0.f;
        for (int a = 0; a < Aa; a++) {
            float w = Ww[h * Aa + a];
            u1 += w * Wa[a];
            u2 += w * Wa[Aa + a];
        }
        g_u1[h] = u1;
        g_u2[h] = u2;
    }
    if (blockIdx.x == 0 && threadIdx.x == 0) {
        float c = 0.f;
        for (int a = 0; a < Aa; a++) c += bw[a] * (Wa[a] + Wa[Aa + a]);
        g_cb = c + ba[0];
    }
}

// ---------------- fused QKV weight build ----------------
__global__ void prep_qkv(const float* __restrict__ Wq, const float* __restrict__ bq,
                         const float* __restrict__ Wk, const float* __restrict__ bk,
                         const float* __restrict__ Wv, const float* __restrict__ bv) {
    int idx = blockIdx.x * 256 + threadIdx.x;
    int row = idx >> 10, c = idx & 1023;
    float v;
    if (c < 128) v = Wq[row * Dd + c];
    else if (c < 256) v = Wk[row * Dd + (c - 128)];
    else v = Wv[row * Hh + (c - 256)];
    g_Wqkv[idx] = v;
    if (row == 0)
        g_bqkv[c] = (c < 128) ? bq[c] : (c < 256) ? bk[c - 128] : bv[c - 256];
}

// ---------------- copy xs -> g_x ----------------
__global__ void copy_x(const float4* __restrict__ src) {
    int i = blockIdx.x * blockDim.x + threadIdx.x;
    ((float4*)g_x)[i] = src[i];
}

// ---------------- gather entity spans + fbias reduce ----------------
__global__ void gather_efea(const float* __restrict__ xs, const int* __restrict__ spans) {
    __shared__ float red[256];
    int bt = blockIdx.x;
    int b = bt / Tt;
    int tid = threadIdx.x;
    int s0 = spans[bt];
    float p = 0.f;
    for (int i = tid; i < Ee * Hh; i += 256) {
        float v = xs[((long)b * Ss + s0 + i / Hh) * Hh + (i % Hh)];
        g_efea[bt * Ee * Hh + i] = v;
        p += v * g_u1[i % Hh];
    }
    red[tid] = p;
    __syncthreads();
    for (int st = 128; st > 0; st >>= 1) {
        if (tid < st) red[tid] += red[tid + st];
        __syncthreads();
    }
    if (tid == 0) g_fbias[bt] = red[0] * (1.f / Ee) + g_cb;
}

// ---------------- q projection: one output per thread, unrolled K ----------------
__global__ void __launch_bounds__(256) qproj(const float* __restrict__ Wq,
                                             const float* __restrict__ bq) {
    int bt = blockIdx.x;
    int tid = threadIdx.x;
    int e = tid >> 5;
    int d = blockIdx.y * 32 + (tid & 31);
    const float* er = &g_efea[bt * Ee * Hh + e * Hh];
    const float* wp = Wq + d;
    float acc = bq[d];
#pragma unroll 8
    for (int h = 0; h < Hh; h++) acc += er[h] * wp[(long)h * Dd];
    g_q[bt * Ee * Dd + e * Dd + d] = acc;
}

// ---------------- qk projection: qk[bt,e,h] = q[bt,e,:].Wk[h,:]; qb = q.bk ----
__global__ void __launch_bounds__(256) qkproj(const float* __restrict__ Wk,
                                              const float* __restrict__ bk) {
    __shared__ float qs[Ee * Dd];
    int bt = blockIdx.x;
    int tid = threadIdx.x;
    for (int i = tid; i < Ee * Dd; i += 256) qs[i] = g_q[bt * Ee * Dd + i];
    __syncthreads();
    int e = tid >> 5, lane = tid & 31;
    int h = blockIdx.y * 32 + lane;
    const float* wr = Wk + (long)h * Dd;
    const float* qr = qs + e * Dd;
    float acc = 0.f;
#pragma unroll 8
    for (int d = 0; d < Dd; d++) acc += qr[d] * wr[d];
    g_qk[bt * Ee * Hh + e * Hh + h] = acc;

    if (blockIdx.y == 0) {
        float p = 0.f;
#pragma unroll
        for (int i = 0; i < 4; i++) p += qr[lane + i * 32] * bk[lane + i * 32];
        for (int off = 16; off > 0; off >>= 1) p += __shfl_xor_sync(0xffffffffu, p, off);
        if (lane == 0) g_qb[bt * Ee + e] = p;
    }
}

// ---------------- fused per-(b,t,n) SDPA (neigh tile resident in smem) ----
// Dynamic smem: tile[Ll*Hh] | qks[Ee*Hh] | p[Ee*Ll] | red[256] | qbs[Ee]
__global__ void __launch_bounds__(256) sdpa_msgs(const float* __restrict__ neigh) {
    extern __shared__ float sm[];
    float* tile = sm;                          // 64 x 768
    float* qks  = tile + Ll * Hh;              // 8 x 768
    float* p    = qks + Ee * Hh;               // 8 x 64
    float* red  = p + Ee * Ll;                 // 256
    float* qbs  = red + 256;                   // 8

    int btn = blockIdx.x;
    int bt = btn / Nn;
    int tid = threadIdx.x;

    long nbase = (long)btn * Ll * Hh;

    // load neigh tile (192 KB, vectorized) + qk + qb
    {
        const float4* src = (const float4*)(neigh + nbase);
        float4* dst = (float4*)tile;
#pragma unroll 8
        for (int i = tid; i < Ll * Hh / 4; i += 256) dst[i] = src[i];
    }
    for (int f = tid; f < Ee * Hh; f += 256) qks[f] = g_qk[bt * Ee * Hh + f];
    if (tid < Ee) qbs[tid] = g_qb[bt * Ee + tid];
    __syncthreads();

    // logits pass: warp w owns l = w*8 .. w*8+7 (reads smem tile)
    {
        int w = tid >> 5, lane = tid & 31;
        for (int li = 0; li < 8; li++) {
            int l = w * 8 + li;
            const float* nr = tile + l * Hh;
            float a0 = 0.f, a1 = 0.f, a2 = 0.f, a3 = 0.f;
            float a4 = 0.f, a5 = 0.f, a6 = 0.f, a7 = 0.f;
#pragma unroll 4
            for (int i = 0; i < Hh / 32; i++) {
                int h = lane + i * 32;
                float v = nr[h];
                a0 += v * qks[0 * Hh + h];
                a1 += v * qks[1 * Hh + h];
                a2 += v * qks[2 * Hh + h];
                a3 += v * qks[3 * Hh + h];
                a4 += v * qks[4 * Hh + h];
                a5 += v * qks[5 * Hh + h];
                a6 += v * qks[6 * Hh + h];
                a7 += v * qks[7 * Hh + h];
            }
#pragma unroll
            for (int off = 16; off > 0; off >>= 1) {
                a0 += __shfl_xor_sync(0xffffffffu, a0, off);
                a1 += __shfl_xor_sync(0xffffffffu, a1, off);
                a2 += __shfl_xor_sync(0xffffffffu, a2, off);
                a3 += __shfl_xor_sync(0xffffffffu, a3, off);
                a4 += __shfl_xor_sync(0xffffffffu, a4, off);
                a5 += __shfl_xor_sync(0xffffffffu, a5, off);
                a6 += __shfl_xor_sync(0xffffffffu, a6, off);
                a7 += __shfl_xor_sync(0xffffffffu, a7, off);
            }
            if (lane == 0) {
                p[0 * Ll + l] = (a0 + qbs[0]) * INV_SQRT_D;
                p[1 * Ll + l] = (a1 + qbs[1]) * INV_SQRT_D;
                p[2 * Ll + l] = (a2 + qbs[2]) * INV_SQRT_D;
                p[3 * Ll + l] = (a3 + qbs[3]) * INV_SQRT_D;
                p[4 * Ll + l] = (a4 + qbs[4]) * INV_SQRT_D;
                p[5 * Ll + l] = (a5 + qbs[5]) * INV_SQRT_D;
                p[6 * Ll + l] = (a6 + qbs[6]) * INV_SQRT_D;
                p[7 * Ll + l] = (a7 + qbs[7]) * INV_SQRT_D;
            }
        }
    }
    __syncthreads();

    // softmax over l per row e (warp w handles row e=w)
    {
        int w = tid >> 5, lane = tid & 31;
        float x0 = p[w * Ll + lane], x1 = p[w * Ll + lane + 32];
        float m = fmaxf(x0, x1);
        for (int off = 16; off > 0; off >>= 1) m = fmaxf(m, __shfl_xor_sync(0xffffffffu, m, off));
        float e0 = expf(x0 - m), e1 = expf(x1 - m);
        float s = e0 + e1;
        for (int off = 16; off > 0; off >>= 1) s += __shfl_xor_sync(0xffffffffu, s, off);
        float r = 1.f / s;
        p[w * Ll + lane] = e0 * r;
        p[w * Ll + lane + 32] = e1 * r;
    }
    __syncthreads();

    // msgs pass (reads smem tile)
    float acc[Ee][3];
#pragma unroll
    for (int e = 0; e < Ee; e++) { acc[e][0] = 0.f; acc[e][1] = 0.f; acc[e][2] = 0.f; }
    for (int l = 0; l < Ll; l++) {
        const float* tr = tile + l * Hh;
        float n0 = tr[tid];
        float n1 = tr[tid + 256];
        float n2 = tr[tid + 512];
#pragma unroll
        for (int e = 0; e < Ee; e++) {
            float pe = p[e * Ll + l];
            acc[e][0] += pe * n0;
            acc[e][1] += pe * n1;
            acc[e][2] += pe * n2;
        }
    }
    long mbase = (long)btn * Ee * Hh;
    float sp = 0.f;
#pragma unroll
    for (int j = 0; j < 3; j++) {
        int h = tid + j * 256;
        float pooled = 0.f;
#pragma unroll
        for (int e = 0; e < Ee; e++) {
            g_msgs[mbase + e * Hh + h] = acc[e][j];
            pooled += acc[e][j];
        }
        sp += pooled * 0.125f * g_u2[h];
    }
    red[tid] = sp;
    __syncthreads();
    for (int st = 128; st > 0; st >>= 1) {
        if (tid < st) red[tid] += red[tid + st];
        __syncthreads();
    }
    if (tid == 0) g_spool[btn] = red[0];
}

// ---------------- neighbor score ----------------
__global__ void score_k(const float* __restrict__ dists, const float* __restrict__ wb,
                        const float* __restrict__ bb) {
    int i = threadIdx.x;
    if (i < Bb * Tt * Nn) {
        float x = g_fbias[i / Nn] + g_spool[i];
        x = x > 0.f ? x : 0.01f * x;
        x += dists[i] * wb[0] + bb[0];
        g_score[i] = 1.f / (1.f + expf(-x));
    }
}

// ---------------- deterministic scatter-add (h-parallel) ----------------
__global__ void scatter_k(const int* __restrict__ spans) {
    __shared__ float sc[Nn];
    int b = blockIdx.x, tid = threadIdx.x;
    int off0 = blockIdx.y * 1024;
    for (int t = 0; t < Tt; t++) {
        int bt = b * Tt + t;
        __syncthreads();
        if (tid < Nn) sc[tid] = g_score[bt * Nn + tid];
        __syncthreads();
        int s0 = spans[bt];
        for (int i = off0 + tid; i < off0 + 1024; i += 256) {
            int e = i / Hh, h = i % Hh;
            float acc = 0.f;
            long base = (long)bt * Nn * Ee * Hh + (long)e * Hh + h;
#pragma unroll 8
            for (int n = 0; n < Nn; n++) acc += sc[n] * g_msgs[base + (long)n * Ee * Hh];
            g_x[((long)b * Ss + s0 + e) * Hh + h] += acc;
        }
    }
}

// ---------------- row softmax over P (512 cols) ----------------
__global__ void softmax_rows() {
    __shared__ float red[256];
    long row = blockIdx.x;
    float* pr = g_P + row * Ss;
    int tid = threadIdx.x;
    float x0 = pr[tid], x1 = pr[tid + 256];
    float m = fmaxf(x0, x1);
    red[tid] = m;
    __syncthreads();
    for (int st = 128; st > 0; st >>= 1) {
        if (tid < st) red[tid] = fmaxf(red[tid], red[tid + st]);
        __syncthreads();
    }
    m = red[0];
    __syncthreads();
    float e0 = expf(x0 - m), e1 = expf(x1 - m);
    red[tid] = e0 + e1;
    __syncthreads();
    for (int st = 128; st > 0; st >>= 1) {
        if (tid < st) red[tid] += red[tid + st];
        __syncthreads();
    }
    float r = 1.f / red[0];
    pr[tid] = e0 * r;
    pr[tid + 256] = e1 * r;
}

// ---------------- launch ----------------
extern "C" void kernel_launch(void* const* d_in, const int* in_sizes, int n_in,
                              void* d_out, int out_size) {
    const float* xs    = (const float*)d_in[0];
    const float* neigh = (const float*)d_in[1];
    const float* dists = (const float*)d_in[2];
    const int*   spans = (const int*)d_in[3];
    const float* Wq = (const float*)d_in[4];
    const float* bq = (const float*)d_in[5];
    const float* Wk = (const float*)d_in[6];
    const float* bk = (const float*)d_in[7];
    const float* Wv = (const float*)d_in[8];
    const float* bv = (const float*)d_in[9];
    const float* Ww = (const float*)d_in[10];
    const float* bw = (const float*)d_in[11];
    const float* Wa = (const float*)d_in[12];
    const float* ba = (const float*)d_in[13];
    const float* wb = (const float*)d_in[14];
    const float* bb = (const float*)d_in[15];
    float* out = (float*)d_out;

    float *px, *pW, *pbias, *pqkv, *pP;
    cudaGetSymbolAddress((void**)&px,    g_x);
    cudaGetSymbolAddress((void**)&pW,    g_Wqkv);
    cudaGetSymbolAddress((void**)&pbias, g_bqkv);
    cudaGetSymbolAddress((void**)&pqkv,  g_qkv);
    cudaGetSymbolAddress((void**)&pP,    g_P);

    // opt-in to large dynamic smem for the sdpa kernel (host attribute, graph-safe)
    static int smem_set = 0;
    if (!smem_set) {
        cudaFuncSetAttribute(sdpa_msgs, cudaFuncAttributeMaxDynamicSharedMemorySize,
                             SDPA_SMEM_BYTES);
        smem_set = 1;
    }

    // Stage 0: precompute + copy
    prep_u<<<3, 256>>>(Ww, Wa, bw, ba);
    prep_qkv<<<(Hh * NQKV) / 256, 256>>>(Wq, bq, Wk, bk, Wv, bv);
    copy_x<<<(Bb * Ss * Hh / 4) / 256, 256>>>((const float4*)xs);
    gather_efea<<<Bb * Tt, 256>>>(xs, spans);
    {
        dim3 g(Bb * Tt, 4);
        qproj<<<g, 256>>>(Wq, bq);
    }
    {
        dim3 g(Bb * Tt, Hh / 32);
        qkproj<<<g, 256>>>(Wk, bk);
    }

    // Stage 1+2 fused: per-neighbor SDPA with smem-resident neigh tile
    sdpa_msgs<<<Bb * Tt * Nn, 256, SDPA_SMEM_BYTES>>>(neigh);

    // Stage 3: neighbor scores + deterministic scatter-add
    score_k<<<1, 1024>>>(dists, wb, bb);
    {
        dim3 g(Bb, 6);
        scatter_k<<<g, 256>>>(spans);
    }

    // Stage 4: fused q2|k2|v2 projection: [8192 x 768] @ [768 x 1024]
    {
        dim3 g(NQKV / 128, (Bb * Ss) / 128, 1);
        tgemm<false><<<g, 256>>>(px, pW, pbias, pqkv,
                                 Bb * Ss, NQKV, Hh, Hh, NQKV, NQKV,
                                 0, 0, 0, 1.f);
    }

    // Stage 5: s2 = q2 @ k2^T * inv_sqrt_d (batched over B), row softmax
    {
        dim3 g(Ss / 128, Ss / 128, Bb);
        tgemm<true><<<g, 256>>>(pqkv /*q2*/, pqkv + 128 /*k2*/, nullptr, pP,
                                Ss, Ss, Dd, NQKV, NQKV, Ss,
                                (long)Ss * NQKV, (long)Ss * NQKV, (long)Ss * Ss,
                                INV_SQRT_D);
    }
    softmax_rows<<<Bb * Ss, 256>>>();

    // Stage 6: out = P @ v2 (batched over B)
    {
        dim3 g(Hh / 128, Ss / 128, Bb);
        tgemm<false><<<g, 256>>>(pP, pqkv + 256 /*v2*/, nullptr, out,
                                 Ss, Hh, Ss, Ss, NQKV, Hh,
                                 (long)Ss * Ss, (long)Ss * NQKV, (long)Ss * Hh,
                                 1.f);
    }
}

// round 14
// speedup vs baseline: 1.1027x; 1.1027x over previous
#include <cuda_runtime.h>
#include <math.h>
#include <stdint.h>

// Problem constants
#define Bb 16
#define Ss 512
#define Hh 768
#define Tt 2
#define Nn 32
#define Ll 64
#define Ee 8
#define Dd 128
#define Aa 128

#define INV_SQRT_D 0.08838834764831845f
#define NQKV 1024   // fused q|k|v output width: 128+128+768

// ---------------- scratch (device globals; no allocation) ----------------
__device__ __align__(16) float g_x[Bb * Ss * Hh];            // updated sequence
__device__ __align__(16) float g_efea[Bb * Tt * Ee * Hh];    // gathered entity spans
__device__ __align__(16) float g_q[Bb * Tt * Ee * Dd];       // entity q proj
__device__ __align__(16) float g_qk[Bb * Tt * Ee * Hh];      // q @ Wk^T (folded k-proj)
__device__ __align__(16) float g_qb[Bb * Tt * Ee];           // q . bk
__device__ __align__(16) float g_msgs[Bb * Tt * Nn * Ee * Hh];
__device__ __align__(16) float g_spool[Bb * Tt * Nn];
__device__ __align__(16) float g_fbias[Bb * Tt];
__device__ __align__(16) float g_score[Bb * Tt * Nn];
__device__ __align__(16) float g_u1[Hh];
__device__ __align__(16) float g_u2[Hh];
__device__ float g_cb;
__device__ __align__(16) float g_Wqkv[Hh * NQKV];   // [768,1024] = Wq|Wk|Wv
__device__ __align__(16) float g_bqkv[NQKV];
__device__ __align__(16) float g_qkv[Bb * Ss * NQKV]; // q2|k2|v2 fused
__device__ __align__(16) float g_P[Bb * Ss * Ss];     // exp(logits), unnormalized
__device__ __align__(16) float g_rs[Bb * Ss];         // row sums of exp

// ---------------- tf32 helpers ----------------
__device__ __forceinline__ uint32_t f2tf(float x) {
    uint32_t r;
    asm("cvt.rna.tf32.f32 %0, %1;" : "=r"(r) : "f"(x));
    return r;
}
__device__ __forceinline__ void mma8(float* c, const uint32_t* a, const uint32_t* b) {
    asm volatile(
        "mma.sync.aligned.m16n8k8.row.col.f32.tf32.tf32.f32 "
        "{%0,%1,%2,%3},{%4,%5,%6,%7},{%8,%9},{%0,%1,%2,%3};"
        : "+f"(c[0]), "+f"(c[1]), "+f"(c[2]), "+f"(c[3])
        : "r"(a[0]), "r"(a[1]), "r"(a[2]), "r"(a[3]), "r"(b[0]), "r"(b[1]));
}

// ---------------- tf32 tensor-core GEMM ----------------
// C[M,N] = alpha * A[M,K] @ B (+ bias[N]); TB=true: B is [N,K] (C = A @ B^T).
// MODE 0: plain; MODE 1: store expf(val), atomically accumulate row sums into rs;
// MODE 2: multiply each row by 1/rs[row].
template <bool TB, int MODE>
__global__ void __launch_bounds__(256, 2) tgemm(
    const float* __restrict__ A, const float* __restrict__ Bm,
    const float* __restrict__ bias, float* __restrict__ C,
    float* __restrict__ rs,
    int M, int N, int K, int lda, int ldb, int ldc,
    long sA, long sB, long sC, float alpha) {
    __shared__ uint32_t As[2][16][132];
    __shared__ uint32_t Bs[2][16][132];
    int tid = threadIdx.x;
    long bz = blockIdx.z;
    A += bz * sA;
    Bm += bz * sB;
    C += bz * sC;
    int row0 = blockIdx.y * 128, col0 = blockIdx.x * 128;
    int wid = tid >> 5, lane = tid & 31;
    int wm = wid >> 2, wn = wid & 3;      // 2 x 4 warp grid
    int gid = lane >> 2, t4 = lane & 3;

    int ar = tid >> 1, ac = (tid & 1) * 8;         // A: 128 rows x 16 k
    const float* Ap = A + (long)(row0 + ar) * lda + ac;
    const float* Bp;
    int br, bc;
    if (TB) {
        br = tid >> 1; bc = (tid & 1) * 8;         // B^T: 128 n-rows x 16 k
        Bp = Bm + (long)(col0 + br) * ldb + bc;
    } else {
        br = tid >> 4; bc = (tid & 15) * 8;        // B: 16 k-rows x 128 n
        Bp = Bm + (long)br * ldb + col0 + bc;
    }

    float4 av0 = *(const float4*)Ap;
    float4 av1 = *(const float4*)(Ap + 4);
    float4 bv0 = *(const float4*)Bp;
    float4 bv1 = *(const float4*)(Bp + 4);

    float acc[4][4][4];
#pragma unroll
    for (int mi = 0; mi < 4; mi++)
#pragma unroll
        for (int ni = 0; ni < 4; ni++)
#pragma unroll
            for (int j = 0; j < 4; j++) acc[mi][ni][j] = 0.f;

    int nst = K / 16;

    {
        As[0][ac + 0][ar] = f2tf(av0.x); As[0][ac + 1][ar] = f2tf(av0.y);
        As[0][ac + 2][ar] = f2tf(av0.z); As[0][ac + 3][ar] = f2tf(av0.w);
        As[0][ac + 4][ar] = f2tf(av1.x); As[0][ac + 5][ar] = f2tf(av1.y);
        As[0][ac + 6][ar] = f2tf(av1.z); As[0][ac + 7][ar] = f2tf(av1.w);
        if (TB) {
            Bs[0][bc + 0][br] = f2tf(bv0.x); Bs[0][bc + 1][br] = f2tf(bv0.y);
            Bs[0][bc + 2][br] = f2tf(bv0.z); Bs[0][bc + 3][br] = f2tf(bv0.w);
            Bs[0][bc + 4][br] = f2tf(bv1.x); Bs[0][bc + 5][br] = f2tf(bv1.y);
            Bs[0][bc + 6][br] = f2tf(bv1.z); Bs[0][bc + 7][br] = f2tf(bv1.w);
        } else {
            uint4 u0 = {f2tf(bv0.x), f2tf(bv0.y), f2tf(bv0.z), f2tf(bv0.w)};
            uint4 u1 = {f2tf(bv1.x), f2tf(bv1.y), f2tf(bv1.z), f2tf(bv1.w)};
            *(uint4*)&Bs[0][br][bc] = u0;
            *(uint4*)&Bs[0][br][bc + 4] = u1;
        }
    }
    __syncthreads();

    for (int t = 0; t < nst; t++) {
        int cur = t & 1;
        if (t + 1 < nst) {
            Ap += 16;
            av0 = *(const float4*)Ap;
            av1 = *(const float4*)(Ap + 4);
            if (TB) Bp += 16; else Bp += (long)16 * ldb;
            bv0 = *(const float4*)Bp;
            bv1 = *(const float4*)(Bp + 4);
        }
#pragma unroll
        for (int kk = 0; kk < 2; kk++) {
            int kb = kk * 8;
            uint32_t af[4][4], bf[4][2];
#pragma unroll
            for (int mi = 0; mi < 4; mi++) {
                int r = wm * 64 + mi * 16 + gid;
                af[mi][0] = As[cur][kb + t4][r];
                af[mi][1] = As[cur][kb + t4][r + 8];
                af[mi][2] = As[cur][kb + t4 + 4][r];
                af[mi][3] = As[cur][kb + t4 + 4][r + 8];
            }
#pragma unroll
            for (int ni = 0; ni < 4; ni++) {
                int c = wn * 32 + ni * 8 + gid;
                bf[ni][0] = Bs[cur][kb + t4][c];
                bf[ni][1] = Bs[cur][kb + t4 + 4][c];
            }
#pragma unroll
            for (int mi = 0; mi < 4; mi++)
#pragma unroll
                for (int ni = 0; ni < 4; ni++) mma8(acc[mi][ni], af[mi], bf[ni]);
        }
        if (t + 1 < nst) {
            int nb = cur ^ 1;
            As[nb][ac + 0][ar] = f2tf(av0.x); As[nb][ac + 1][ar] = f2tf(av0.y);
            As[nb][ac + 2][ar] = f2tf(av0.z); As[nb][ac + 3][ar] = f2tf(av0.w);
            As[nb][ac + 4][ar] = f2tf(av1.x); As[nb][ac + 5][ar] = f2tf(av1.y);
            As[nb][ac + 6][ar] = f2tf(av1.z); As[nb][ac + 7][ar] = f2tf(av1.w);
            if (TB) {
                Bs[nb][bc + 0][br] = f2tf(bv0.x); Bs[nb][bc + 1][br] = f2tf(bv0.y);
                Bs[nb][bc + 2][br] = f2tf(bv0.z); Bs[nb][bc + 3][br] = f2tf(bv0.w);
                Bs[nb][bc + 4][br] = f2tf(bv1.x); Bs[nb][bc + 5][br] = f2tf(bv1.y);
                Bs[nb][bc + 6][br] = f2tf(bv1.z); Bs[nb][bc + 7][br] = f2tf(bv1.w);
            } else {
                uint4 u0 = {f2tf(bv0.x), f2tf(bv0.y), f2tf(bv0.z), f2tf(bv0.w)};
                uint4 u1 = {f2tf(bv1.x), f2tf(bv1.y), f2tf(bv1.z), f2tf(bv1.w)};
                *(uint4*)&Bs[nb][br][bc] = u0;
                *(uint4*)&Bs[nb][br][bc + 4] = u1;
            }
            __syncthreads();
        }
    }

    // epilogue
#pragma unroll
    for (int mi = 0; mi < 4; mi++) {
        int row = row0 + wm * 64 + mi * 16 + gid;
        float r0s = 0.f, r1s = 0.f;
        float d0 = 1.f, d1 = 1.f;
        if (MODE == 2) {
            d0 = 1.f / rs[bz * M + row];
            d1 = 1.f / rs[bz * M + row + 8];
        }
#pragma unroll
        for (int ni = 0; ni < 4; ni++) {
            int col = col0 + wn * 32 + ni * 8 + t4 * 2;
            float b0 = bias ? bias[col] : 0.f;
            float b1 = bias ? bias[col + 1] : 0.f;
            float v00 = acc[mi][ni][0] * alpha + b0;
            float v01 = acc[mi][ni][1] * alpha + b1;
            float v10 = acc[mi][ni][2] * alpha + b0;
            float v11 = acc[mi][ni][3] * alpha + b1;
            if (MODE == 1) {
                v00 = expf(v00); v01 = expf(v01);
                v10 = expf(v10); v11 = expf(v11);
                r0s += v00 + v01;
                r1s += v10 + v11;
            } else if (MODE == 2) {
                v00 *= d0; v01 *= d0;
                v10 *= d1; v11 *= d1;
            }
            float2 o0 = {v00, v01};
            float2 o1 = {v10, v11};
            *(float2*)&C[(long)row * ldc + col] = o0;
            *(float2*)&C[(long)(row + 8) * ldc + col] = o1;
        }
        if (MODE == 1) {
            r0s += __shfl_xor_sync(0xffffffffu, r0s, 1);
            r0s += __shfl_xor_sync(0xffffffffu, r0s, 2);
            r1s += __shfl_xor_sync(0xffffffffu, r1s, 1);
            r1s += __shfl_xor_sync(0xffffffffu, r1s, 2);
            if (t4 == 0) {
                atomicAdd(&rs[bz * M + row], r0s);
                atomicAdd(&rs[bz * M + row + 8], r1s);
            }
        }
    }
}

// ---------------- fused prep: QKV weight build + u1/u2/cb ----------------
__global__ void prep_all(const float* __restrict__ Wq, const float* __restrict__ bq,
                         const float* __restrict__ Wk, const float* __restrict__ bk,
                         const float* __restrict__ Wv, const float* __restrict__ bv,
                         const float* __restrict__ Ww, const float* __restrict__ Wa,
                         const float* __restrict__ bw, const float* __restrict__ ba) {
    int idx = blockIdx.x * 256 + threadIdx.x;
    int row = idx >> 10, c = idx & 1023;
    float v;
    if (c < 128) v = Wq[row * Dd + c];
    else if (c < 256) v = Wk[row * Dd + (c - 128)];
    else v = Wv[row * Hh + (c - 256)];
    g_Wqkv[idx] = v;
    if (row == 0)
        g_bqkv[c] = (c < 128) ? bq[c] : (c < 256) ? bk[c - 128] : bv[c - 256];

    if (blockIdx.x < 3) {
        int h = blockIdx.x * 256 + threadIdx.x;
        if (h < Hh) {
            float u1 = 0.f, u2 = 0.f;
            for (int a = 0; a < Aa; a++) {
                float w = Ww[h * Aa + a];
                u1 += w * Wa[a];
                u2 += w * Wa[Aa + a];
            }
            g_u1[h] = u1;
            g_u2[h] = u2;
        }
        if (blockIdx.x == 0 && threadIdx.x == 0) {
            float cc = 0.f;
            for (int a = 0; a < Aa; a++) cc += bw[a] * (Wa[a] + Wa[Aa + a]);
            g_cb = cc + ba[0];
        }
    }
}

// ---------------- copy xs -> g_x ----------------
__global__ void copy_x(const float4* __restrict__ src) {
    int i = blockIdx.x * blockDim.x + threadIdx.x;
    ((float4*)g_x)[i] = src[i];
}

// ---------------- gather entity spans + fbias reduce ----------------
__global__ void gather_efea(const float* __restrict__ xs, const int* __restrict__ spans) {
    __shared__ float red[256];
    int bt = blockIdx.x;
    int b = bt / Tt;
    int tid = threadIdx.x;
    int s0 = spans[bt];
    float p = 0.f;
    for (int i = tid; i < Ee * Hh; i += 256) {
        float v = xs[((long)b * Ss + s0 + i / Hh) * Hh + (i % Hh)];
        g_efea[bt * Ee * Hh + i] = v;
        p += v * g_u1[i % Hh];
    }
    red[tid] = p;
    __syncthreads();
    for (int st = 128; st > 0; st >>= 1) {
        if (tid < st) red[tid] += red[tid + st];
        __syncthreads();
    }
    if (tid == 0) g_fbias[bt] = red[0] * (1.f / Ee) + g_cb;
}

// ---------------- q projection: one output per thread, unrolled K ----------------
__global__ void __launch_bounds__(256) qproj(const float* __restrict__ Wq,
                                             const float* __restrict__ bq) {
    int bt = blockIdx.x;
    int tid = threadIdx.x;
    int e = tid >> 5;
    int d = blockIdx.y * 32 + (tid & 31);
    const float* er = &g_efea[bt * Ee * Hh + e * Hh];
    const float* wp = Wq + d;
    float acc = bq[d];
#pragma unroll 8
    for (int h = 0; h < Hh; h++) acc += er[h] * wp[(long)h * Dd];
    g_q[bt * Ee * Dd + e * Dd + d] = acc;
}

// ---------------- qk projection: qk[bt,e,h] = q[bt,e,:].Wk[h,:]; qb = q.bk ----
__global__ void __launch_bounds__(256) qkproj(const float* __restrict__ Wk,
                                              const float* __restrict__ bk) {
    __shared__ float qs[Ee * Dd];
    int bt = blockIdx.x;
    int tid = threadIdx.x;
    for (int i = tid; i < Ee * Dd; i += 256) qs[i] = g_q[bt * Ee * Dd + i];
    __syncthreads();
    int e = tid >> 5, lane = tid & 31;
    int h = blockIdx.y * 32 + lane;
    const float* wr = Wk + (long)h * Dd;
    const float* qr = qs + e * Dd;
    float acc = 0.f;
#pragma unroll 8
    for (int d = 0; d < Dd; d++) acc += qr[d] * wr[d];
    g_qk[bt * Ee * Hh + e * Hh + h] = acc;

    if (blockIdx.y == 0) {
        float p = 0.f;
#pragma unroll
        for (int i = 0; i < 4; i++) p += qr[lane + i * 32] * bk[lane + i * 32];
        for (int off = 16; off > 0; off >>= 1) p += __shfl_xor_sync(0xffffffffu, p, off);
        if (lane == 0) g_qb[bt * Ee + e] = p;
    }
}

// ---------------- fused per-(b,t,n) SDPA (round-12 version: global reads) ----
__global__ void __launch_bounds__(256) sdpa_msgs(const float* __restrict__ neigh) {
    __shared__ float qks[Ee * Hh];   // 24KB
    __shared__ float p[Ee * Ll];
    __shared__ float red[256];
    __shared__ float qbs[Ee];
    int btn = blockIdx.x;
    int bt = btn / Nn;
    int tid = threadIdx.x;

    for (int f = tid; f < Ee * Hh; f += 256) qks[f] = g_qk[bt * Ee * Hh + f];
    if (tid < Ee) qbs[tid] = g_qb[bt * Ee + tid];
    __syncthreads();

    long nbase = (long)btn * Ll * Hh;

    // logits pass: warp w owns l = w*8 .. w*8+7
    {
        int w = tid >> 5, lane = tid & 31;
        for (int li = 0; li < 8; li++) {
            int l = w * 8 + li;
            const float* nr = neigh + nbase + (long)l * Hh;
            float a0 = 0.f, a1 = 0.f, a2 = 0.f, a3 = 0.f;
            float a4 = 0.f, a5 = 0.f, a6 = 0.f, a7 = 0.f;
#pragma unroll 4
            for (int i = 0; i < Hh / 32; i++) {
                int h = lane + i * 32;
                float v = nr[h];
                a0 += v * qks[0 * Hh + h];
                a1 += v * qks[1 * Hh + h];
                a2 += v * qks[2 * Hh + h];
                a3 += v * qks[3 * Hh + h];
                a4 += v * qks[4 * Hh + h];
                a5 += v * qks[5 * Hh + h];
                a6 += v * qks[6 * Hh + h];
                a7 += v * qks[7 * Hh + h];
            }
#pragma unroll
            for (int off = 16; off > 0; off >>= 1) {
                a0 += __shfl_xor_sync(0xffffffffu, a0, off);
                a1 += __shfl_xor_sync(0xffffffffu, a1, off);
                a2 += __shfl_xor_sync(0xffffffffu, a2, off);
                a3 += __shfl_xor_sync(0xffffffffu, a3, off);
                a4 += __shfl_xor_sync(0xffffffffu, a4, off);
                a5 += __shfl_xor_sync(0xffffffffu, a5, off);
                a6 += __shfl_xor_sync(0xffffffffu, a6, off);
                a7 += __shfl_xor_sync(0xffffffffu, a7, off);
            }
            if (lane == 0) {
                p[0 * Ll + l] = (a0 + qbs[0]) * INV_SQRT_D;
                p[1 * Ll + l] = (a1 + qbs[1]) * INV_SQRT_D;
                p[2 * Ll + l] = (a2 + qbs[2]) * INV_SQRT_D;
                p[3 * Ll + l] = (a3 + qbs[3]) * INV_SQRT_D;
                p[4 * Ll + l] = (a4 + qbs[4]) * INV_SQRT_D;
                p[5 * Ll + l] = (a5 + qbs[5]) * INV_SQRT_D;
                p[6 * Ll + l] = (a6 + qbs[6]) * INV_SQRT_D;
                p[7 * Ll + l] = (a7 + qbs[7]) * INV_SQRT_D;
            }
        }
    }
    __syncthreads();

    // softmax over l per row e (warp w handles row e=w)
    {
        int w = tid >> 5, lane = tid & 31;
        float x0 = p[w * Ll + lane], x1 = p[w * Ll + lane + 32];
        float m = fmaxf(x0, x1);
        for (int off = 16; off > 0; off >>= 1) m = fmaxf(m, __shfl_xor_sync(0xffffffffu, m, off));
        float e0 = expf(x0 - m), e1 = expf(x1 - m);
        float s = e0 + e1;
        for (int off = 16; off > 0; off >>= 1) s += __shfl_xor_sync(0xffffffffu, s, off);
        float r = 1.f / s;
        p[w * Ll + lane] = e0 * r;
        p[w * Ll + lane + 32] = e1 * r;
    }
    __syncthreads();

    // msgs pass (neigh re-read mostly hits L2)
    float acc[Ee][3];
#pragma unroll
    for (int e = 0; e < Ee; e++) { acc[e][0] = 0.f; acc[e][1] = 0.f; acc[e][2] = 0.f; }
    for (int l = 0; l < Ll; l++) {
        float n0 = neigh[nbase + l * Hh + tid];
        float n1 = neigh[nbase + l * Hh + tid + 256];
        float n2 = neigh[nbase + l * Hh + tid + 512];
#pragma unroll
        for (int e = 0; e < Ee; e++) {
            float pe = p[e * Ll + l];
            acc[e][0] += pe * n0;
            acc[e][1] += pe * n1;
            acc[e][2] += pe * n2;
        }
    }
    long mbase = (long)btn * Ee * Hh;
    float sp = 0.f;
#pragma unroll
    for (int j = 0; j < 3; j++) {
        int h = tid + j * 256;
        float pooled = 0.f;
#pragma unroll
        for (int e = 0; e < Ee; e++) {
            g_msgs[mbase + e * Hh + h] = acc[e][j];
            pooled += acc[e][j];
        }
        sp += pooled * 0.125f * g_u2[h];
    }
    red[tid] = sp;
    __syncthreads();
    for (int st = 128; st > 0; st >>= 1) {
        if (tid < st) red[tid] += red[tid + st];
        __syncthreads();
    }
    if (tid == 0) g_spool[btn] = red[0];
}

// ---------------- neighbor score + zero rowsum buffer ----------------
__global__ void score_k(const float* __restrict__ dists, const float* __restrict__ wb,
                        const float* __restrict__ bb) {
    int i = threadIdx.x;
    if (i < Bb * Tt * Nn) {
        float x = g_fbias[i / Nn] + g_spool[i];
        x = x > 0.f ? x : 0.01f * x;
        x += dists[i] * wb[0] + bb[0];
        g_score[i] = 1.f / (1.f + expf(-x));
    }
    for (int j = i; j < Bb * Ss; j += 1024) g_rs[j] = 0.f;
}

// ---------------- deterministic scatter-add (h-parallel) ----------------
__global__ void scatter_k(const int* __restrict__ spans) {
    __shared__ float sc[Nn];
    int b = blockIdx.x, tid = threadIdx.x;
    int off0 = blockIdx.y * 1024;
    for (int t = 0; t < Tt; t++) {
        int bt = b * Tt + t;
        __syncthreads();
        if (tid < Nn) sc[tid] = g_score[bt * Nn + tid];
        __syncthreads();
        int s0 = spans[bt];
        for (int i = off0 + tid; i < off0 + 1024; i += 256) {
            int e = i / Hh, h = i % Hh;
            float acc = 0.f;
            long base = (long)bt * Nn * Ee * Hh + (long)e * Hh + h;
#pragma unroll 8
            for (int n = 0; n < Nn; n++) acc += sc[n] * g_msgs[base + (long)n * Ee * Hh];
            g_x[((long)b * Ss + s0 + e) * Hh + h] += acc;
        }
    }
}

// ---------------- launch ----------------
extern "C" void kernel_launch(void* const* d_in, const int* in_sizes, int n_in,
                              void* d_out, int out_size) {
    const float* xs    = (const float*)d_in[0];
    const float* neigh = (const float*)d_in[1];
    const float* dists = (const float*)d_in[2];
    const int*   spans = (const int*)d_in[3];
    const float* Wq = (const float*)d_in[4];
    const float* bq = (const float*)d_in[5];
    const float* Wk = (const float*)d_in[6];
    const float* bk = (const float*)d_in[7];
    const float* Wv = (const float*)d_in[8];
    const float* bv = (const float*)d_in[9];
    const float* Ww = (const float*)d_in[10];
    const float* bw = (const float*)d_in[11];
    const float* Wa = (const float*)d_in[12];
    const float* ba = (const float*)d_in[13];
    const float* wb = (const float*)d_in[14];
    const float* bb = (const float*)d_in[15];
    float* out = (float*)d_out;

    float *px, *pW, *pbias, *pqkv, *pP, *prs;
    cudaGetSymbolAddress((void**)&px,    g_x);
    cudaGetSymbolAddress((void**)&pW,    g_Wqkv);
    cudaGetSymbolAddress((void**)&pbias, g_bqkv);
    cudaGetSymbolAddress((void**)&pqkv,  g_qkv);
    cudaGetSymbolAddress((void**)&pP,    g_P);
    cudaGetSymbolAddress((void**)&prs,   g_rs);

    // Stage 0: precompute + copy
    prep_all<<<(Hh * NQKV) / 256, 256>>>(Wq, bq, Wk, bk, Wv, bv, Ww, Wa, bw, ba);
    copy_x<<<(Bb * Ss * Hh / 4) / 256, 256>>>((const float4*)xs);
    gather_efea<<<Bb * Tt, 256>>>(xs, spans);
    {
        dim3 g(Bb * Tt, 4);
        qproj<<<g, 256>>>(Wq, bq);
    }
    {
        dim3 g(Bb * Tt, Hh / 32);
        qkproj<<<g, 256>>>(Wk, bk);
    }

    // Stage 1+2 fused: per-neighbor SDPA with folded k-projection
    sdpa_msgs<<<Bb * Tt * Nn, 256>>>(neigh);

    // Stage 3: neighbor scores (+ rowsum zero) + deterministic scatter-add
    score_k<<<1, 1024>>>(dists, wb, bb);
    {
        dim3 g(Bb, 6);
        scatter_k<<<g, 256>>>(spans);
    }

    // Stage 4: fused q2|k2|v2 projection: [8192 x 768] @ [768 x 1024]
    {
        dim3 g(NQKV / 128, (Bb * Ss) / 128, 1);
        tgemm<false, 0><<<g, 256>>>(px, pW, pbias, pqkv, nullptr,
                                    Bb * Ss, NQKV, Hh, Hh, NQKV, NQKV,
                                    0, 0, 0, 1.f);
    }

    // Stage 5: P = exp(q2 @ k2^T * inv_sqrt_d), row sums into g_rs (batched)
    {
        dim3 g(Ss / 128, Ss / 128, Bb);
        tgemm<true, 1><<<g, 256>>>(pqkv /*q2*/, pqkv + 128 /*k2*/, nullptr, pP, prs,
                                   Ss, Ss, Dd, NQKV, NQKV, Ss,
                                   (long)Ss * NQKV, (long)Ss * NQKV, (long)Ss * Ss,
                                   INV_SQRT_D);
    }

    // Stage 6: out = (P @ v2) / rowsum (batched)
    {
        dim3 g(Hh / 128, Ss / 128, Bb);
        tgemm<false, 2><<<g, 256>>>(pP, pqkv + 256 /*v2*/, nullptr, out, prs,
                                    Ss, Hh, Ss, Ss, NQKV, Hh,
                                    (long)Ss * Ss, (long)Ss * NQKV, (long)Ss * Hh,
                                    1.f);
    }
}

// round 16
// speedup vs baseline: 1.2493x; 1.1329x over previous
#include <cuda_runtime.h>
#include <math.h>
#include <stdint.h>

// Problem constants
#define Bb 16
#define Ss 512
#define Hh 768
#define Tt 2
#define Nn 32
#define Ll 64
#define Ee 8
#define Dd 128
#define Aa 128

#define INV_SQRT_D 0.08838834764831845f
#define NQKV 1024   // fused q|k|v output width: 128+128+768

// ---------------- scratch (device globals; no allocation) ----------------
__device__ __align__(16) float g_x[Bb * Ss * Hh];            // updated sequence
__device__ __align__(16) float g_efea[Bb * Tt * Ee * Hh];    // gathered entity spans
__device__ __align__(16) float g_qk[Bb * Tt * Ee * Hh];      // folded q@Wk^T
__device__ __align__(16) float g_qb[Bb * Tt * Ee];           // q . bk
__device__ __align__(16) float g_msgs[Bb * Tt * Nn * Ee * Hh];
__device__ __align__(16) float g_spool[Bb * Tt * Nn];
__device__ __align__(16) float g_fbias[Bb * Tt];
__device__ __align__(16) float g_score[Bb * Tt * Nn];
__device__ __align__(16) float g_u1[Hh];
__device__ __align__(16) float g_u2[Hh];
__device__ float g_cb;
__device__ __align__(16) float g_vq[Hh];      // Wq @ bk
__device__ __align__(16) float g_bqWk[Hh];    // bq . Wk[h,:]
__device__ float g_cqb;                       // bq . bk
__device__ __align__(16) float g_Mqk[Hh * Hh]; // Wq @ Wk^T
__device__ __align__(16) float g_Wqkv[Hh * NQKV];   // [768,1024] = Wq|Wk|Wv
__device__ __align__(16) float g_bqkv[NQKV];
__device__ __align__(16) float g_qkv[Bb * Ss * NQKV]; // q2|k2|v2 fused
__device__ __align__(16) float g_P[Bb * Ss * Ss];     // exp(logits), unnormalized
__device__ __align__(16) float g_rs[Bb * Ss];         // row sums of exp

// ---------------- tf32 helpers ----------------
__device__ __forceinline__ uint32_t f2tf(float x) {
    uint32_t r;
    asm("cvt.rna.tf32.f32 %0, %1;" : "=r"(r) : "f"(x));
    return r;
}
__device__ __forceinline__ void mma8(float* c, const uint32_t* a, const uint32_t* b) {
    asm volatile(
        "mma.sync.aligned.m16n8k8.row.col.f32.tf32.tf32.f32 "
        "{%0,%1,%2,%3},{%4,%5,%6,%7},{%8,%9},{%0,%1,%2,%3};"
        : "+f"(c[0]), "+f"(c[1]), "+f"(c[2]), "+f"(c[3])
        : "r"(a[0]), "r"(a[1]), "r"(a[2]), "r"(a[3]), "r"(b[0]), "r"(b[1]));
}

// ---------------- tf32 tensor-core GEMM ----------------
// C[M,N] = alpha * A[M,K] @ B (+ bias[N]); TB=true: B is [N,K] (C = A @ B^T).
// MODE 0: plain; MODE 1: store expf(val), atomically accumulate row sums into rs;
// MODE 2: multiply each row by 1/rs[row].
template <bool TB, int MODE>
__global__ void __launch_bounds__(256, 2) tgemm(
    const float* __restrict__ A, const float* __restrict__ Bm,
    const float* __restrict__ bias, float* __restrict__ C,
    float* __restrict__ rs,
    int M, int N, int K, int lda, int ldb, int ldc,
    long sA, long sB, long sC, float alpha) {
    __shared__ uint32_t As[2][16][132];
    __shared__ uint32_t Bs[2][16][132];
    int tid = threadIdx.x;
    long bz = blockIdx.z;
    A += bz * sA;
    Bm += bz * sB;
    C += bz * sC;
    int row0 = blockIdx.y * 128, col0 = blockIdx.x * 128;
    int wid = tid >> 5, lane = tid & 31;
    int wm = wid >> 2, wn = wid & 3;      // 2 x 4 warp grid
    int gid = lane >> 2, t4 = lane & 3;

    int ar = tid >> 1, ac = (tid & 1) * 8;         // A: 128 rows x 16 k
    const float* Ap = A + (long)(row0 + ar) * lda + ac;
    const float* Bp;
    int br, bc;
    if (TB) {
        br = tid >> 1; bc = (tid & 1) * 8;         // B^T: 128 n-rows x 16 k
        Bp = Bm + (long)(col0 + br) * ldb + bc;
    } else {
        br = tid >> 4; bc = (tid & 15) * 8;        // B: 16 k-rows x 128 n
        Bp = Bm + (long)br * ldb + col0 + bc;
    }

    float4 av0 = *(const float4*)Ap;
    float4 av1 = *(const float4*)(Ap + 4);
    float4 bv0 = *(const float4*)Bp;
    float4 bv1 = *(const float4*)(Bp + 4);

    float acc[4][4][4];
#pragma unroll
    for (int mi = 0; mi < 4; mi++)
#pragma unroll
        for (int ni = 0; ni < 4; ni++)
#pragma unroll
            for (int j = 0; j < 4; j++) acc[mi][ni][j] = 0.f;

    int nst = K / 16;

    {
        As[0][ac + 0][ar] = f2tf(av0.x); As[0][ac + 1][ar] = f2tf(av0.y);
        As[0][ac + 2][ar] = f2tf(av0.z); As[0][ac + 3][ar] = f2tf(av0.w);
        As[0][ac + 4][ar] = f2tf(av1.x); As[0][ac + 5][ar] = f2tf(av1.y);
        As[0][ac + 6][ar] = f2tf(av1.z); As[0][ac + 7][ar] = f2tf(av1.w);
        if (TB) {
            Bs[0][bc + 0][br] = f2tf(bv0.x); Bs[0][bc + 1][br] = f2tf(bv0.y);
            Bs[0][bc + 2][br] = f2tf(bv0.z); Bs[0][bc + 3][br] = f2tf(bv0.w);
            Bs[0][bc + 4][br] = f2tf(bv1.x); Bs[0][bc + 5][br] = f2tf(bv1.y);
            Bs[0][bc + 6][br] = f2tf(bv1.z); Bs[0][bc + 7][br] = f2tf(bv1.w);
        } else {
            uint4 u0 = {f2tf(bv0.x), f2tf(bv0.y), f2tf(bv0.z), f2tf(bv0.w)};
            uint4 u1 = {f2tf(bv1.x), f2tf(bv1.y), f2tf(bv1.z), f2tf(bv1.w)};
            *(uint4*)&Bs[0][br][bc] = u0;
            *(uint4*)&Bs[0][br][bc + 4] = u1;
        }
    }
    __syncthreads();

    for (int t = 0; t < nst; t++) {
        int cur = t & 1;
        if (t + 1 < nst) {
            Ap += 16;
            av0 = *(const float4*)Ap;
            av1 = *(const float4*)(Ap + 4);
            if (TB) Bp += 16; else Bp += (long)16 * ldb;
            bv0 = *(const float4*)Bp;
            bv1 = *(const float4*)(Bp + 4);
        }
#pragma unroll
        for (int kk = 0; kk < 2; kk++) {
            int kb = kk * 8;
            uint32_t af[4][4], bf[4][2];
#pragma unroll
            for (int mi = 0; mi < 4; mi++) {
                int r = wm * 64 + mi * 16 + gid;
                af[mi][0] = As[cur][kb + t4][r];
                af[mi][1] = As[cur][kb + t4][r + 8];
                af[mi][2] = As[cur][kb + t4 + 4][r];
                af[mi][3] = As[cur][kb + t4 + 4][r + 8];
            }
#pragma unroll
            for (int ni = 0; ni < 4; ni++) {
                int c = wn * 32 + ni * 8 + gid;
                bf[ni][0] = Bs[cur][kb + t4][c];
                bf[ni][1] = Bs[cur][kb + t4 + 4][c];
            }
#pragma unroll
            for (int mi = 0; mi < 4; mi++)
#pragma unroll
                for (int ni = 0; ni < 4; ni++) mma8(acc[mi][ni], af[mi], bf[ni]);
        }
        if (t + 1 < nst) {
            int nb = cur ^ 1;
            As[nb][ac + 0][ar] = f2tf(av0.x); As[nb][ac + 1][ar] = f2tf(av0.y);
            As[nb][ac + 2][ar] = f2tf(av0.z); As[nb][ac + 3][ar] = f2tf(av0.w);
            As[nb][ac + 4][ar] = f2tf(av1.x); As[nb][ac + 5][ar] = f2tf(av1.y);
            As[nb][ac + 6][ar] = f2tf(av1.z); As[nb][ac + 7][ar] = f2tf(av1.w);
            if (TB) {
                Bs[nb][bc + 0][br] = f2tf(bv0.x); Bs[nb][bc + 1][br] = f2tf(bv0.y);
                Bs[nb][bc + 2][br] = f2tf(bv0.z); Bs[nb][bc + 3][br] = f2tf(bv0.w);
                Bs[nb][bc + 4][br] = f2tf(bv1.x); Bs[nb][bc + 5][br] = f2tf(bv1.y);
                Bs[nb][bc + 6][br] = f2tf(bv1.z); Bs[nb][bc + 7][br] = f2tf(bv1.w);
            } else {
                uint4 u0 = {f2tf(bv0.x), f2tf(bv0.y), f2tf(bv0.z), f2tf(bv0.w)};
                uint4 u1 = {f2tf(bv1.x), f2tf(bv1.y), f2tf(bv1.z), f2tf(bv1.w)};
                *(uint4*)&Bs[nb][br][bc] = u0;
                *(uint4*)&Bs[nb][br][bc + 4] = u1;
            }
            __syncthreads();
        }
    }

    // epilogue
#pragma unroll
    for (int mi = 0; mi < 4; mi++) {
        int row = row0 + wm * 64 + mi * 16 + gid;
        float r0s = 0.f, r1s = 0.f;
        float d0 = 1.f, d1 = 1.f;
        if (MODE == 2) {
            d0 = 1.f / rs[bz * M + row];
            d1 = 1.f / rs[bz * M + row + 8];
        }
#pragma unroll
        for (int ni = 0; ni < 4; ni++) {
            int col = col0 + wn * 32 + ni * 8 + t4 * 2;
            float b0 = bias ? bias[col] : 0.f;
            float b1 = bias ? bias[col + 1] : 0.f;
            float v00 = acc[mi][ni][0] * alpha + b0;
            float v01 = acc[mi][ni][1] * alpha + b1;
            float v10 = acc[mi][ni][2] * alpha + b0;
            float v11 = acc[mi][ni][3] * alpha + b1;
            if (MODE == 1) {
                v00 = expf(v00); v01 = expf(v01);
                v10 = expf(v10); v11 = expf(v11);
                r0s += v00 + v01;
                r1s += v10 + v11;
            } else if (MODE == 2) {
                v00 *= d0; v01 *= d0;
                v10 *= d1; v11 *= d1;
            }
            float2 o0 = {v00, v01};
            float2 o1 = {v10, v11};
            *(float2*)&C[(long)row * ldc + col] = o0;
            *(float2*)&C[(long)(row + 8) * ldc + col] = o1;
        }
        if (MODE == 1) {
            r0s += __shfl_xor_sync(0xffffffffu, r0s, 1);
            r0s += __shfl_xor_sync(0xffffffffu, r0s, 2);
            r1s += __shfl_xor_sync(0xffffffffu, r1s, 1);
            r1s += __shfl_xor_sync(0xffffffffu, r1s, 2);
            if (t4 == 0) {
                atomicAdd(&rs[bz * M + row], r0s);
                atomicAdd(&rs[bz * M + row + 8], r1s);
            }
        }
    }
}

// ---------------- fused prep: QKV weight build + u1/u2/cb + vq/bqWk/cqb ----
__global__ void prep_all(const float* __restrict__ Wq, const float* __restrict__ bq,
                         const float* __restrict__ Wk, const float* __restrict__ bk,
                         const float* __restrict__ Wv, const float* __restrict__ bv,
                         const float* __restrict__ Ww, const float* __restrict__ Wa,
                         const float* __restrict__ bw, const float* __restrict__ ba) {
    int idx = blockIdx.x * 256 + threadIdx.x;
    int row = idx >> 10, c = idx & 1023;
    float v;
    if (c < 128) v = Wq[row * Dd + c];
    else if (c < 256) v = Wk[row * Dd + (c - 128)];
    else v = Wv[row * Hh + (c - 256)];
    g_Wqkv[idx] = v;
    if (row == 0)
        g_bqkv[c] = (c < 128) ? bq[c] : (c < 256) ? bk[c - 128] : bv[c - 256];

    if (blockIdx.x < 3) {
        int h = blockIdx.x * 256 + threadIdx.x;
        if (h < Hh) {
            float u1 = 0.f, u2 = 0.f;
            for (int a = 0; a < Aa; a++) {
                float w = Ww[h * Aa + a];
                u1 += w * Wa[a];
                u2 += w * Wa[Aa + a];
            }
            g_u1[h] = u1;
            g_u2[h] = u2;
        }
        if (blockIdx.x == 0 && threadIdx.x == 0) {
            float cc = 0.f;
            for (int a = 0; a < Aa; a++) cc += bw[a] * (Wa[a] + Wa[Aa + a]);
            g_cb = cc + ba[0];
        }
    } else if (blockIdx.x < 6) {
        int h = (blockIdx.x - 3) * 256 + threadIdx.x;   // 0..767
        float v1 = 0.f, v2 = 0.f;
        for (int d = 0; d < Dd; d++) {
            v1 += Wq[h * Dd + d] * bk[d];
            v2 += bq[d] * Wk[h * Dd + d];
        }
        g_vq[h] = v1;
        g_bqWk[h] = v2;
        if (blockIdx.x == 3 && threadIdx.x == 0) {
            float cc = 0.f;
            for (int d = 0; d < Dd; d++) cc += bq[d] * bk[d];
            g_cqb = cc;
        }
    }
}

// ---------------- copy xs -> g_x ----------------
__global__ void copy_x(const float4* __restrict__ src) {
    int i = blockIdx.x * blockDim.x + threadIdx.x;
    ((float4*)g_x)[i] = src[i];
}

// ---------------- gather entity spans + fbias reduce ----------------
__global__ void gather_efea(const float* __restrict__ xs, const int* __restrict__ spans) {
    __shared__ float red[256];
    int bt = blockIdx.x;
    int b = bt / Tt;
    int tid = threadIdx.x;
    int s0 = spans[bt];
    float p = 0.f;
    for (int i = tid; i < Ee * Hh; i += 256) {
        float v = xs[((long)b * Ss + s0 + i / Hh) * Hh + (i % Hh)];
        g_efea[bt * Ee * Hh + i] = v;
        p += v * g_u1[i % Hh];
    }
    red[tid] = p;
    __syncthreads();
    for (int st = 128; st > 0; st >>= 1) {
        if (tid < st) red[tid] += red[tid + st];
        __syncthreads();
    }
    if (tid == 0) g_fbias[bt] = red[0] * (1.f / Ee) + g_cb;
}

// ---------------- qb: g_qb[bt,e] = efea[bt,e,:].vq + cqb ----------------
// grid 32, block 256 = 8 warps; warp e reduces over h
__global__ void __launch_bounds__(256) qbproj() {
    int bt = blockIdx.x;
    int e = threadIdx.x >> 5, lane = threadIdx.x & 31;
    const float* er = &g_efea[bt * Ee * Hh + e * Hh];
    float p = 0.f;
#pragma unroll
    for (int i = 0; i < Hh / 32; i++) p += er[lane + i * 32] * g_vq[lane + i * 32];
    for (int off = 16; off > 0; off >>= 1) p += __shfl_xor_sync(0xffffffffu, p, off);
    if (lane == 0) g_qb[bt * Ee + e] = p + g_cqb;
}

// ---------------- fused per-(b,t,n) SDPA (logits from qk . neigh) ----------
__global__ void __launch_bounds__(256) sdpa_msgs(const float* __restrict__ neigh) {
    __shared__ float qks[Ee * Hh];   // 24KB
    __shared__ float p[Ee * Ll];
    __shared__ float red[256];
    __shared__ float qbs[Ee];
    int btn = blockIdx.x;
    int bt = btn / Nn;
    int tid = threadIdx.x;

    for (int f = tid; f < Ee * Hh; f += 256) qks[f] = g_qk[bt * Ee * Hh + f];
    if (tid < Ee) qbs[tid] = g_qb[bt * Ee + tid];
    __syncthreads();

    long nbase = (long)btn * Ll * Hh;

    // logits pass: warp w owns l = w*8 .. w*8+7
    {
        int w = tid >> 5, lane = tid & 31;
        for (int li = 0; li < 8; li++) {
            int l = w * 8 + li;
            const float* nr = neigh + nbase + (long)l * Hh;
            float a0 = 0.f, a1 = 0.f, a2 = 0.f, a3 = 0.f;
            float a4 = 0.f, a5 = 0.f, a6 = 0.f, a7 = 0.f;
#pragma unroll 4
            for (int i = 0; i < Hh / 32; i++) {
                int h = lane + i * 32;
                float v = nr[h];
                a0 += v * qks[0 * Hh + h];
                a1 += v * qks[1 * Hh + h];
                a2 += v * qks[2 * Hh + h];
                a3 += v * qks[3 * Hh + h];
                a4 += v * qks[4 * Hh + h];
                a5 += v * qks[5 * Hh + h];
                a6 += v * qks[6 * Hh + h];
                a7 += v * qks[7 * Hh + h];
            }
#pragma unroll
            for (int off = 16; off > 0; off >>= 1) {
                a0 += __shfl_xor_sync(0xffffffffu, a0, off);
                a1 += __shfl_xor_sync(0xffffffffu, a1, off);
                a2 += __shfl_xor_sync(0xffffffffu, a2, off);
                a3 += __shfl_xor_sync(0xffffffffu, a3, off);
                a4 += __shfl_xor_sync(0xffffffffu, a4, off);
                a5 += __shfl_xor_sync(0xffffffffu, a5, off);
                a6 += __shfl_xor_sync(0xffffffffu, a6, off);
                a7 += __shfl_xor_sync(0xffffffffu, a7, off);
            }
            if (lane == 0) {
                p[0 * Ll + l] = (a0 + qbs[0]) * INV_SQRT_D;
                p[1 * Ll + l] = (a1 + qbs[1]) * INV_SQRT_D;
                p[2 * Ll + l] = (a2 + qbs[2]) * INV_SQRT_D;
                p[3 * Ll + l] = (a3 + qbs[3]) * INV_SQRT_D;
                p[4 * Ll + l] = (a4 + qbs[4]) * INV_SQRT_D;
                p[5 * Ll + l] = (a5 + qbs[5]) * INV_SQRT_D;
                p[6 * Ll + l] = (a6 + qbs[6]) * INV_SQRT_D;
                p[7 * Ll + l] = (a7 + qbs[7]) * INV_SQRT_D;
            }
        }
    }
    __syncthreads();

    // softmax over l per row e (warp w handles row e=w)
    {
        int w = tid >> 5, lane = tid & 31;
        float x0 = p[w * Ll + lane], x1 = p[w * Ll + lane + 32];
        float m = fmaxf(x0, x1);
        for (int off = 16; off > 0; off >>= 1) m = fmaxf(m, __shfl_xor_sync(0xffffffffu, m, off));
        float e0 = expf(x0 - m), e1 = expf(x1 - m);
        float s = e0 + e1;
        for (int off = 16; off > 0; off >>= 1) s += __shfl_xor_sync(0xffffffffu, s, off);
        float r = 1.f / s;
        p[w * Ll + lane] = e0 * r;
        p[w * Ll + lane + 32] = e1 * r;
    }
    __syncthreads();

    // msgs pass (neigh re-read mostly hits L2)
    float acc[Ee][3];
#pragma unroll
    for (int e = 0; e < Ee; e++) { acc[e][0] = 0.f; acc[e][1] = 0.f; acc[e][2] = 0.f; }
    for (int l = 0; l < Ll; l++) {
        float n0 = neigh[nbase + l * Hh + tid];
        float n1 = neigh[nbase + l * Hh + tid + 256];
        float n2 = neigh[nbase + l * Hh + tid + 512];
#pragma unroll
        for (int e = 0; e < Ee; e++) {
            float pe = p[e * Ll + l];
            acc[e][0] += pe * n0;
            acc[e][1] += pe * n1;
            acc[e][2] += pe * n2;
        }
    }
    long mbase = (long)btn * Ee * Hh;
    float sp = 0.f;
#pragma unroll
    for (int j = 0; j < 3; j++) {
        int h = tid + j * 256;
        float pooled = 0.f;
#pragma unroll
        for (int e = 0; e < Ee; e++) {
            g_msgs[mbase + e * Hh + h] = acc[e][j];
            pooled += acc[e][j];
        }
        sp += pooled * 0.125f * g_u2[h];
    }
    red[tid] = sp;
    __syncthreads();
    for (int st = 128; st > 0; st >>= 1) {
        if (tid < st) red[tid] += red[tid + st];
        __syncthreads();
    }
    if (tid == 0) g_spool[btn] = red[0];
}

// ---------------- neighbor score + zero rowsum buffer ----------------
__global__ void score_k(const float* __restrict__ dists, const float* __restrict__ wb,
                        const float* __restrict__ bb) {
    int i = threadIdx.x;
    if (i < Bb * Tt * Nn) {
        float x = g_fbias[i / Nn] + g_spool[i];
        x = x > 0.f ? x : 0.01f * x;
        x += dists[i] * wb[0] + bb[0];
        g_score[i] = 1.f / (1.f + expf(-x));
    }
    for (int j = i; j < Bb * Ss; j += 1024) g_rs[j] = 0.f;
}

// ---------------- deterministic scatter-add (h-parallel) ----------------
__global__ void scatter_k(const int* __restrict__ spans) {
    __shared__ float sc[Nn];
    int b = blockIdx.x, tid = threadIdx.x;
    int off0 = blockIdx.y * 1024;
    for (int t = 0; t < Tt; t++) {
        int bt = b * Tt + t;
        __syncthreads();
        if (tid < Nn) sc[tid] = g_score[bt * Nn + tid];
        __syncthreads();
        int s0 = spans[bt];
        for (int i = off0 + tid; i < off0 + 1024; i += 256) {
            int e = i / Hh, h = i % Hh;
            float acc = 0.f;
            long base = (long)bt * Nn * Ee * Hh + (long)e * Hh + h;
#pragma unroll 8
            for (int n = 0; n < Nn; n++) acc += sc[n] * g_msgs[base + (long)n * Ee * Hh];
            g_x[((long)b * Ss + s0 + e) * Hh + h] += acc;
        }
    }
}

// ---------------- launch ----------------
extern "C" void kernel_launch(void* const* d_in, const int* in_sizes, int n_in,
                              void* d_out, int out_size) {
    const float* xs    = (const float*)d_in[0];
    const float* neigh = (const float*)d_in[1];
    const float* dists = (const float*)d_in[2];
    const int*   spans = (const int*)d_in[3];
    const float* Wq = (const float*)d_in[4];
    const float* bq = (const float*)d_in[5];
    const float* Wk = (const float*)d_in[6];
    const float* bk = (const float*)d_in[7];
    const float* Wv = (const float*)d_in[8];
    const float* bv = (const float*)d_in[9];
    const float* Ww = (const float*)d_in[10];
    const float* bw = (const float*)d_in[11];
    const float* Wa = (const float*)d_in[12];
    const float* ba = (const float*)d_in[13];
    const float* wb = (const float*)d_in[14];
    const float* bb = (const float*)d_in[15];
    float* out = (float*)d_out;

    float *px, *pW, *pbias, *pqkv, *pP, *prs, *pMqk, *pbqWk, *pefea, *pqk;
    cudaGetSymbolAddress((void**)&px,    g_x);
    cudaGetSymbolAddress((void**)&pW,    g_Wqkv);
    cudaGetSymbolAddress((void**)&pbias, g_bqkv);
    cudaGetSymbolAddress((void**)&pqkv,  g_qkv);
    cudaGetSymbolAddress((void**)&pP,    g_P);
    cudaGetSymbolAddress((void**)&prs,   g_rs);
    cudaGetSymbolAddress((void**)&pMqk,  g_Mqk);
    cudaGetSymbolAddress((void**)&pbqWk, g_bqWk);
    cudaGetSymbolAddress((void**)&pefea, g_efea);
    cudaGetSymbolAddress((void**)&pqk,   g_qk);

    // Stage 0: precompute + copy
    prep_all<<<(Hh * NQKV) / 256, 256>>>(Wq, bq, Wk, bk, Wv, bv, Ww, Wa, bw, ba);
    copy_x<<<(Bb * Ss * Hh / 4) / 256, 256>>>((const float4*)xs);

    // Mqk = Wq @ Wk^T : [768 x 768], K=128 (tensor core)
    {
        dim3 g(Hh / 128, Hh / 128, 1);
        tgemm<true, 0><<<g, 256>>>(Wq, Wk, nullptr, pMqk, nullptr,
                                   Hh, Hh, Dd, Dd, Dd, Hh, 0, 0, 0, 1.f);
    }

    gather_efea<<<Bb * Tt, 256>>>(xs, spans);

    // qk = efea @ Mqk + bqWk : [256 x 768], K=768 (tensor core)
    {
        dim3 g(Hh / 128, (Bb * Tt * Ee) / 128, 1);
        tgemm<false, 0><<<g, 256>>>(pefea, pMqk, pbqWk, pqk, nullptr,
                                    Bb * Tt * Ee, Hh, Hh, Hh, Hh, Hh,
                                    0, 0, 0, 1.f);
    }
    qbproj<<<Bb * Tt, 256>>>();

    // Stage 1+2 fused: per-neighbor SDPA with folded k-projection
    sdpa_msgs<<<Bb * Tt * Nn, 256>>>(neigh);

    // Stage 3: neighbor scores (+ rowsum zero) + deterministic scatter-add
    score_k<<<1, 1024>>>(dists, wb, bb);
    {
        dim3 g(Bb, 6);
        scatter_k<<<g, 256>>>(spans);
    }

    // Stage 4: fused q2|k2|v2 projection: [8192 x 768] @ [768 x 1024]
    {
        dim3 g(NQKV / 128, (Bb * Ss) / 128, 1);
        tgemm<false, 0><<<g, 256>>>(px, pW, pbias, pqkv, nullptr,
                                    Bb * Ss, NQKV, Hh, Hh, NQKV, NQKV,
                                    0, 0, 0, 1.f);
    }

    // Stage 5: P = exp(q2 @ k2^T * inv_sqrt_d), row sums into g_rs (batched)
    {
        dim3 g(Ss / 128, Ss / 128, Bb);
        tgemm<true, 1><<<g, 256>>>(pqkv /*q2*/, pqkv + 128 /*k2*/, nullptr, pP, prs,
                                   Ss, Ss, Dd, NQKV, NQKV, Ss,
                                   (long)Ss * NQKV, (long)Ss * NQKV, (long)Ss * Ss,
                                   INV_SQRT_D);
    }

    // Stage 6: out = (P @ v2) / rowsum (batched)
    {
        dim3 g(Hh / 128, Ss / 128, Bb);
        tgemm<false, 2><<<g, 256>>>(pP, pqkv + 256 /*v2*/, nullptr, out, prs,
                                    Ss, Hh, Ss, Ss, NQKV, Hh,
                                    (long)Ss * Ss, (long)Ss * NQKV, (long)Ss * Hh,
                                    1.f);
    }
}